// round 16
// baseline (speedup 1.0000x reference)
#include <cuda_runtime.h>
#include <cuda_bf16.h>

// Problem constants (fixed shapes for this benchmark)
#define GN 65536
#define GD 512
#define GC 64

// ------------------------- device scratch (static, no allocation) ---------
__device__ __align__(16) float g_psum[GC * GD];    // per-class sums [C][D]
__device__ __align__(16) float g_protoT[GD * GC];  // prototypes, k-major [D][C]
__device__ __align__(16) float g_p2[GC];           // ||p_c||^2
__device__ int   g_counts[GC];
__device__ int   g_offsets[GC];
__device__ int   g_cursor[GC];
__device__ __align__(16) int g_sorted[GN];         // row indices sorted by class
__device__ float g_loss;
__device__ int   g_correct;
__device__ int   g_is64;                           // labels dtype flag
__device__ int   g_hist_done;                      // last-block ticket for fused scan

// ------------------------- label accessor (dtype-agnostic) ------------------
__device__ __forceinline__ int get_label(const void* lab, int i) {
    if (g_is64) return (int)((const long long*)lab)[i];
    return ((const int*)lab)[i];
}

// ------------------------- f32x2 helpers -----------------------------------
__device__ __forceinline__ void ffma2(unsigned long long& d,
                                      unsigned long long a,
                                      unsigned long long b) {
    asm("fma.rn.f32x2 %0, %1, %2, %0;" : "+l"(d) : "l"(a), "l"(b));
}
__device__ __forceinline__ unsigned long long dup2(float x) {
    unsigned long long r;
    unsigned u = __float_as_uint(x);
    asm("mov.b64 %0, {%1, %1};" : "=l"(r) : "r"(u));
    return r;
}

// ------------------------- K0: zero scratch + dtype probe -------------------
// Probe: if labels are int64 (values 0..63), every odd 32-bit word is zero.
__global__ void k_zero(const int* labels32) {
    int i = blockIdx.x * blockDim.x + threadIdx.x;
    if (i < GC * GD) g_psum[i] = 0.0f;
    if (i < GC) g_counts[i] = 0;
    if (i == 0) {
        g_loss = 0.0f;
        g_correct = 0;
        g_hist_done = 0;
        int s = 0;
        for (int j = 1; j < 128; j += 2) s |= labels32[j];
        g_is64 = (s == 0) ? 1 : 0;
    }
}

// ------------------------- K1: histogram + fused exclusive scan -------------
__global__ void k_hist(const void* __restrict__ labels) {
    __shared__ int h[GC];
    __shared__ int isLast;
    if (threadIdx.x < GC) h[threadIdx.x] = 0;
    __syncthreads();
    for (int i = blockIdx.x * blockDim.x + threadIdx.x; i < GN;
         i += gridDim.x * blockDim.x) {
        atomicAdd(&h[get_label(labels, i) & (GC - 1)], 1);
    }
    __syncthreads();
    if (threadIdx.x < GC) atomicAdd(&g_counts[threadIdx.x], h[threadIdx.x]);
    __threadfence();
    if (threadIdx.x == 0)
        isLast = (atomicAdd(&g_hist_done, 1) == (int)gridDim.x - 1);
    __syncthreads();
    // Last block to finish performs the scan with a single warp (2 vals/lane,
    // shfl-only: no divergent __syncthreads).
    if (isLast && threadIdx.x < 32) {
        __threadfence();  // acquire counts written by other blocks
        int l = threadIdx.x;
        int c0 = l * 2;
        int a = g_counts[c0], b = g_counts[c0 + 1];
        int x = a + b;
#pragma unroll
        for (int o = 1; o < 32; o <<= 1) {
            int y = __shfl_up_sync(0xffffffffu, x, o);
            if (l >= o) x += y;
        }
        int excl = x - (a + b);  // exclusive prefix of pair
        g_offsets[c0] = excl;
        g_cursor[c0] = excl;
        g_offsets[c0 + 1] = excl + a;
        g_cursor[c0 + 1] = excl + a;
    }
}

// ------------------------- K2: scatter sort by class ------------------------
__global__ void k_scatter(const void* __restrict__ labels) {
    int i = blockIdx.x * blockDim.x + threadIdx.x;
    if (i < GN) {
        int c = get_label(labels, i) & (GC - 1);
        int pos = atomicAdd(&g_cursor[c], 1);
        g_sorted[pos] = i;
    }
}

// ------------------------- K3: per-class sums (conflict-free) ---------------
__global__ void k_psum(const float* __restrict__ emb) {
    int c = blockIdx.x >> 3;
    int chunk = blockIdx.x & 7;
    int cnt = g_counts[c];
    int off = g_offsets[c];
    int s = off + (int)(((long long)cnt * chunk) >> 3);
    int e = off + (int)(((long long)cnt * (chunk + 1)) >> 3);
    int d = threadIdx.x;
    float acc = 0.0f;
    int r = s;
    for (; r + 4 <= e; r += 4) {
        int i0 = g_sorted[r + 0];
        int i1 = g_sorted[r + 1];
        int i2 = g_sorted[r + 2];
        int i3 = g_sorted[r + 3];
        float v0 = emb[(size_t)i0 * GD + d];
        float v1 = emb[(size_t)i1 * GD + d];
        float v2 = emb[(size_t)i2 * GD + d];
        float v3 = emb[(size_t)i3 * GD + d];
        acc += v0 + v1 + v2 + v3;
    }
    for (; r < e; r++) acc += emb[(size_t)g_sorted[r] * GD + d];
    atomicAdd(&g_psum[c * GD + d], acc);
}

// ------------------------- K4: finalize prototypes + p2 ---------------------
__global__ void k_proto() {
    int c = blockIdx.x;
    int d = threadIdx.x;  // 512 threads
    float cnt = (float)g_counts[c];
    float p = g_psum[c * GD + d] / cnt;
    g_protoT[d * GC + c] = p;  // k-major for GEMM B operand
    float s = p * p;
#pragma unroll
    for (int o = 16; o; o >>= 1) s += __shfl_xor_sync(0xffffffffu, s, o);
    __shared__ float w[16];
    int wid = threadIdx.x >> 5, lane = threadIdx.x & 31;
    if (lane == 0) w[wid] = s;
    __syncthreads();
    if (threadIdx.x < 16) {
        float x = w[threadIdx.x];
#pragma unroll
        for (int o = 8; o; o >>= 1) x += __shfl_xor_sync(0xffffu, x, o);
        if (threadIdx.x == 0) g_p2[c] = x;
    }
}

// ------------------------- K5: GEMM + fused e2 + fused epilogue -------------
// Tile: 256 rows x 64 cols, K=512 streamed in 32-chunks, 512 threads.
// fp32x2 packed FMA (FFMA2), A row-pairs packed as 64-bit operands.
// e2 (row squared norms) is accumulated from the loader fragments: each row is
// covered by exactly 8 consecutive lanes (k4 = 0..7) across 16 chunks.
#define BM 256
#define BK 32
#define AS_OFF 32768                 // after Bs (512*64 floats)
#define E2_OFF (AS_OFF + 2 * BK * BM)
#define P2_OFF (E2_OFF + BM)
#define RED_OFF (P2_OFF + GC)
#define SMEM_FLOATS (RED_OFF + 2)
#define SMEM_BYTES (SMEM_FLOATS * 4)
#define CPAD 65                      // cross-tile row stride (bank-conflict-free)

__global__ __launch_bounds__(512, 1) void k_main(
    const float* __restrict__ emb, const void* __restrict__ labels) {
    extern __shared__ float sm[];
    float* Bs = sm;                 // [512][64] prototypes, k-major (FULL K)
    float* As = sm + AS_OFF;        // [2][32][256] A tile, k-major, swizzled
    float* s_e2 = sm + E2_OFF;      // [256]
    float* s_p2 = sm + P2_OFF;      // [64]
    float* s_loss = sm + RED_OFF;
    int* s_corr = (int*)(sm + RED_OFF + 1);

    const int tid = threadIdx.x;
    const int row0 = blockIdx.x * BM;

    // Load full prototype matrix into SMEM (contiguous, coalesced)
    {
        const float4* src = (const float4*)g_protoT;
        float4* dst = (float4*)Bs;
#pragma unroll
        for (int i = tid; i < (GD * GC) / 4; i += 512) dst[i] = src[i];
    }
    if (tid < GC) s_p2[tid] = g_p2[tid];
    if (tid == 0) { *s_loss = 0.0f; *s_corr = 0; }

    const int tx = tid & 15;   // col group: cols tx*4 .. tx*4+3
    const int ty = tid >> 4;   // row group: rows ty*8 .. ty*8+7
    const int ty8 = ty * 8;
    const int tx4 = tx * 4;

    unsigned long long acc[4][4];
#pragma unroll
    for (int p = 0; p < 4; p++)
#pragma unroll
        for (int n = 0; n < 4; n++) acc[p][n] = 0ULL;

    // Loader mapping: idx = tid + it*512; r = idx>>3 (row), k4 = idx&7
    int lr[4], lk4[4];
#pragma unroll
    for (int it = 0; it < 4; it++) {
        int idx = tid + it * 512;
        lr[it] = idx >> 3;
        lk4[it] = idx & 7;
    }
    float4 v[4];
    float e2p[4] = {0.0f, 0.0f, 0.0f, 0.0f};

#define LOAD_CHUNK(T)                                                        \
    {                                                                        \
        _Pragma("unroll") for (int it = 0; it < 4; it++) {                   \
            v[it] = *(const float4*)(emb + (size_t)(row0 + lr[it]) * GD +    \
                                     (T)*BK + lk4[it] * 4);                  \
        }                                                                    \
        _Pragma("unroll") for (int it = 0; it < 4; it++) {                   \
            e2p[it] += v[it].x * v[it].x + v[it].y * v[it].y +               \
                       v[it].z * v[it].z + v[it].w * v[it].w;                \
        }                                                                    \
    }
#define STORE_CHUNK(BUF)                                                     \
    {                                                                        \
        float* A = As + (BUF) * (BK * BM);                                   \
        _Pragma("unroll") for (int it = 0; it < 4; it++) {                   \
            int rr = lr[it], k4 = lk4[it];                                   \
            int col = rr ^ (k4 << 2); /* XOR swizzle -> conflict-free */     \
            float* p = A + (k4 * 4) * BM + col;                              \
            p[0 * BM] = v[it].x;                                             \
            p[1 * BM] = v[it].y;                                             \
            p[2 * BM] = v[it].z;                                             \
            p[3 * BM] = v[it].w;                                             \
        }                                                                    \
    }

    LOAD_CHUNK(0);
    STORE_CHUNK(0);
    __syncthreads();

    // Single barrier per iteration: STORE targets buffer buf^1, whose readers
    // (iteration t-1's compute) were all fenced by the barrier that ended
    // iteration t-1. Compute reads buf, written before the same barrier.
#pragma unroll 1
    for (int t = 0; t < GD / BK; t++) {
        const int buf = t & 1;
        if (t + 1 < GD / BK) LOAD_CHUNK(t + 1);  // overlap LDG with compute
        const float* A = As + buf * (BK * BM);
        const float* Brow = Bs + t * BK * GC;
#pragma unroll
        for (int k = 0; k < BK; k++) {
            const int sw = k & 28;  // (k>>2)<<2 : matches store swizzle
            const float* arow = A + k * BM;
            ulonglong2 a01 =
                *(const ulonglong2*)(arow + ((ty8 + 0) ^ sw));  // rows ty8+0..3
            ulonglong2 a23 =
                *(const ulonglong2*)(arow + ((ty8 + 4) ^ sw));  // rows ty8+4..7
            float4 bv = *(const float4*)(Brow + k * GC + tx4);
            unsigned long long b0 = dup2(bv.x);
            unsigned long long b1 = dup2(bv.y);
            unsigned long long b2 = dup2(bv.z);
            unsigned long long b3 = dup2(bv.w);
            ffma2(acc[0][0], a01.x, b0);
            ffma2(acc[0][1], a01.x, b1);
            ffma2(acc[0][2], a01.x, b2);
            ffma2(acc[0][3], a01.x, b3);
            ffma2(acc[1][0], a01.y, b0);
            ffma2(acc[1][1], a01.y, b1);
            ffma2(acc[1][2], a01.y, b2);
            ffma2(acc[1][3], a01.y, b3);
            ffma2(acc[2][0], a23.x, b0);
            ffma2(acc[2][1], a23.x, b1);
            ffma2(acc[2][2], a23.x, b2);
            ffma2(acc[2][3], a23.x, b3);
            ffma2(acc[3][0], a23.y, b0);
            ffma2(acc[3][1], a23.y, b1);
            ffma2(acc[3][2], a23.y, b2);
            ffma2(acc[3][3], a23.y, b3);
        }
        if (t + 1 < GD / BK) STORE_CHUNK((t + 1) & 1);
        __syncthreads();
    }

    // e2: reduce across the 8 lanes sharing each row, write to s_e2
#pragma unroll
    for (int it = 0; it < 4; it++) {
        float s = e2p[it];
        s += __shfl_xor_sync(0xffffffffu, s, 4);
        s += __shfl_xor_sync(0xffffffffu, s, 2);
        s += __shfl_xor_sync(0xffffffffu, s, 1);
        if ((tid & 7) == 0) s_e2[(tid >> 3) + it * 64] = s;
    }

    // Spill cross-products into (now dead) Bs/As region, padded stride 65
    float* s_cross = Bs;  // [256][CPAD] floats = 66560 B < 192 KB region
#pragma unroll
    for (int p = 0; p < 4; p++) {
#pragma unroll
        for (int n = 0; n < 4; n++) {
            unsigned long long a = acc[p][n];
            float lo = __uint_as_float((unsigned)(a & 0xffffffffULL));
            float hi = __uint_as_float((unsigned)(a >> 32));
            s_cross[(ty8 + 2 * p + 0) * CPAD + tx4 + n] = lo;
            s_cross[(ty8 + 2 * p + 1) * CPAD + tx4 + n] = hi;
        }
    }
    __syncthreads();

    // Per-row epilogue: distances -> logits -> log-softmax -> nll / argmax
    if (tid < BM) {
        const int r = tid;
        const int lab = get_label(labels, row0 + r) & (GC - 1);
        const float e2 = s_e2[r];
        float* cr = s_cross + r * CPAD;
        float mx = -3.0e38f;
        int bi = 0;
#pragma unroll 8
        for (int c = 0; c < GC; c++) {
            float d2 = e2 + s_p2[c] - 2.0f * cr[c];
            d2 = fmaxf(d2, 1e-12f);
            float lg = -sqrtf(d2);
            cr[c] = lg;  // overwrite in place
            if (lg > mx) { mx = lg; bi = c; }
        }
        float se = 0.0f;
#pragma unroll 8
        for (int c = 0; c < GC; c++) se += __expf(cr[c] - mx);
        float nll = (mx + __logf(se)) - cr[lab];
        atomicAdd(s_loss, nll);
        if (bi == lab) atomicAdd(s_corr, 1);
    }
    __syncthreads();
    if (tid == 0) {
        atomicAdd(&g_loss, *s_loss);
        atomicAdd(&g_correct, *s_corr);
    }
#undef LOAD_CHUNK
#undef STORE_CHUNK
}

// ------------------------- K6: finalize outputs -----------------------------
__global__ void k_final(float* out, int out_size) {
    if (threadIdx.x == 0 && blockIdx.x == 0) {
        out[0] = g_loss / (float)GN;
        if (out_size > 1) out[1] = (float)g_correct / (float)GN;
    }
}

// ------------------------- launch -------------------------------------------
extern "C" void kernel_launch(void* const* d_in, const int* in_sizes, int n_in,
                              void* d_out, int out_size) {
    const float* emb = (const float*)d_in[0];
    const void* labels = d_in[1];
    float* out = (float*)d_out;

    cudaFuncSetAttribute(k_main, cudaFuncAttributeMaxDynamicSharedMemorySize,
                         SMEM_BYTES);

    k_zero<<<(GC * GD + 255) / 256, 256>>>((const int*)labels);
    k_hist<<<64, 256>>>(labels);
    k_scatter<<<GN / 256, 256>>>(labels);
    k_psum<<<GC * 8, 512>>>(emb);
    k_proto<<<GC, 512>>>();
    k_main<<<GN / BM, 512, SMEM_BYTES>>>(emb, labels);
    k_final<<<1, 32>>>(out, out_size);
}

// round 17
// speedup vs baseline: 1.6537x; 1.6537x over previous
#include <cuda_runtime.h>
#include <cuda_bf16.h>

// Problem constants (fixed shapes for this benchmark)
#define GN 65536
#define GD 512
#define GC 64

// ------------------------- device scratch (static, no allocation) ---------
__device__ __align__(16) float g_psum[GC * GD];    // per-class sums [C][D]
__device__ __align__(16) float g_protoT[GD * GC];  // prototypes, k-major [D][C]
__device__ __align__(16) float g_p2[GC];           // ||p_c||^2
__device__ int   g_counts[GC];
__device__ int   g_offsets[GC];
__device__ int   g_cursor[GC];
__device__ __align__(16) int g_sorted[GN];         // row indices sorted by class
__device__ __align__(16) float g_e2[GN];           // ||e_i||^2 (atomic-accumulated)
__device__ float g_loss;
__device__ int   g_correct;
__device__ int   g_is64;                           // labels dtype flag
__device__ int   g_hist_done;                      // last-block ticket for fused scan

// ------------------------- label accessor (dtype-agnostic) ------------------
__device__ __forceinline__ int get_label(const void* lab, int i) {
    if (g_is64) return (int)((const long long*)lab)[i];
    return ((const int*)lab)[i];
}

// ------------------------- f32x2 helpers -----------------------------------
__device__ __forceinline__ void ffma2(unsigned long long& d,
                                      unsigned long long a,
                                      unsigned long long b) {
    asm("fma.rn.f32x2 %0, %1, %2, %0;" : "+l"(d) : "l"(a), "l"(b));
}
__device__ __forceinline__ unsigned long long dup2(float x) {
    unsigned long long r;
    unsigned u = __float_as_uint(x);
    asm("mov.b64 %0, {%1, %1};" : "=l"(r) : "r"(u));
    return r;
}

// ------------------------- K0: zero scratch + dtype probe -------------------
__global__ void k_zero(const int* labels32) {
    int i = blockIdx.x * blockDim.x + threadIdx.x;
    if (i < GC * GD) g_psum[i] = 0.0f;
    if (i < GN) g_e2[i] = 0.0f;
    if (i < GC) g_counts[i] = 0;
    if (i == 0) {
        g_loss = 0.0f;
        g_correct = 0;
        g_hist_done = 0;
        int s = 0;
        for (int j = 1; j < 128; j += 2) s |= labels32[j];
        g_is64 = (s == 0) ? 1 : 0;
    }
}

// ------------------------- K1: histogram + fused exclusive scan -------------
__global__ void k_hist(const void* __restrict__ labels) {
    __shared__ int h[GC];
    __shared__ int isLast;
    if (threadIdx.x < GC) h[threadIdx.x] = 0;
    __syncthreads();
    for (int i = blockIdx.x * blockDim.x + threadIdx.x; i < GN;
         i += gridDim.x * blockDim.x) {
        atomicAdd(&h[get_label(labels, i) & (GC - 1)], 1);
    }
    __syncthreads();
    if (threadIdx.x < GC) atomicAdd(&g_counts[threadIdx.x], h[threadIdx.x]);
    __threadfence();
    if (threadIdx.x == 0)
        isLast = (atomicAdd(&g_hist_done, 1) == (int)gridDim.x - 1);
    __syncthreads();
    if (isLast && threadIdx.x < 32) {
        __threadfence();
        int l = threadIdx.x;
        int c0 = l * 2;
        int a = g_counts[c0], b = g_counts[c0 + 1];
        int x = a + b;
#pragma unroll
        for (int o = 1; o < 32; o <<= 1) {
            int y = __shfl_up_sync(0xffffffffu, x, o);
            if (l >= o) x += y;
        }
        int excl = x - (a + b);
        g_offsets[c0] = excl;
        g_cursor[c0] = excl;
        g_offsets[c0 + 1] = excl + a;
        g_cursor[c0 + 1] = excl + a;
    }
}

// ------------------------- K2: scatter sort by class ------------------------
__global__ void k_scatter(const void* __restrict__ labels) {
    int i = blockIdx.x * blockDim.x + threadIdx.x;
    if (i < GN) {
        int c = get_label(labels, i) & (GC - 1);
        int pos = atomicAdd(&g_cursor[c], 1);
        g_sorted[pos] = i;
    }
}

// ------------------------- K3: per-class sums + fused e2 --------------------
// 4 groups of 128 threads per block; each group owns one 1/8-chunk of one
// class. Thread covers dims [gt*4, gt*4+4) via float4 -> each row is read by
// one group with a single fully-coalesced 512B access per warp-quad.
// 8-row unroll: 128B in flight per thread. e2 fused: warp shfl-reduce of
// sum(v*v) + 4 spread-address atomics per row.
__global__ __launch_bounds__(512) void k_psum(const float* __restrict__ emb) {
    const int tid = threadIdx.x;
    const int grp = tid >> 7;        // 0..3
    const int gt = tid & 127;        // thread within group
    const int group_global = blockIdx.x * 4 + grp;  // 0..511
    const int c = group_global >> 3;
    const int chunk = group_global & 7;
    const int cnt = g_counts[c];
    const int off = g_offsets[c];
    const int s = off + (int)(((long long)cnt * chunk) >> 3);
    const int e = off + (int)(((long long)cnt * (chunk + 1)) >> 3);
    const int lane4 = gt * 4;
    const bool wlead = ((gt & 31) == 0);

    float4 acc = {0.0f, 0.0f, 0.0f, 0.0f};
    int r = s;
    for (; r + 8 <= e; r += 8) {
        int idx[8];
#pragma unroll
        for (int j = 0; j < 8; j++) idx[j] = g_sorted[r + j];  // uniform bcast
        float4 vv[8];
#pragma unroll
        for (int j = 0; j < 8; j++)
            vv[j] = *(const float4*)(emb + (size_t)idx[j] * GD + lane4);
#pragma unroll
        for (int j = 0; j < 8; j++) {
            float4 v = vv[j];
            acc.x += v.x;
            acc.y += v.y;
            acc.z += v.z;
            acc.w += v.w;
            float sq = v.x * v.x + v.y * v.y + v.z * v.z + v.w * v.w;
            sq += __shfl_xor_sync(0xffffffffu, sq, 16);
            sq += __shfl_xor_sync(0xffffffffu, sq, 8);
            sq += __shfl_xor_sync(0xffffffffu, sq, 4);
            sq += __shfl_xor_sync(0xffffffffu, sq, 2);
            sq += __shfl_xor_sync(0xffffffffu, sq, 1);
            if (wlead) atomicAdd(&g_e2[idx[j]], sq);
        }
    }
    for (; r < e; r++) {
        int i0 = g_sorted[r];
        float4 v = *(const float4*)(emb + (size_t)i0 * GD + lane4);
        acc.x += v.x;
        acc.y += v.y;
        acc.z += v.z;
        acc.w += v.w;
        float sq = v.x * v.x + v.y * v.y + v.z * v.z + v.w * v.w;
        sq += __shfl_xor_sync(0xffffffffu, sq, 16);
        sq += __shfl_xor_sync(0xffffffffu, sq, 8);
        sq += __shfl_xor_sync(0xffffffffu, sq, 4);
        sq += __shfl_xor_sync(0xffffffffu, sq, 2);
        sq += __shfl_xor_sync(0xffffffffu, sq, 1);
        if (wlead) atomicAdd(&g_e2[i0], sq);
    }
    float* dst = &g_psum[c * GD + lane4];
    atomicAdd(dst + 0, acc.x);
    atomicAdd(dst + 1, acc.y);
    atomicAdd(dst + 2, acc.z);
    atomicAdd(dst + 3, acc.w);
}

// ------------------------- K4: finalize prototypes + p2 ---------------------
__global__ void k_proto() {
    int c = blockIdx.x;
    int d = threadIdx.x;  // 512 threads
    float cnt = (float)g_counts[c];
    float p = g_psum[c * GD + d] / cnt;
    g_protoT[d * GC + c] = p;  // k-major for GEMM B operand
    float s = p * p;
#pragma unroll
    for (int o = 16; o; o >>= 1) s += __shfl_xor_sync(0xffffffffu, s, o);
    __shared__ float w[16];
    int wid = threadIdx.x >> 5, lane = threadIdx.x & 31;
    if (lane == 0) w[wid] = s;
    __syncthreads();
    if (threadIdx.x < 16) {
        float x = w[threadIdx.x];
#pragma unroll
        for (int o = 8; o; o >>= 1) x += __shfl_xor_sync(0xffffu, x, o);
        if (threadIdx.x == 0) g_p2[c] = x;
    }
}

// ------------------------- K5: GEMM + fused epilogue (R15-proven) -----------
// Tile: 256 rows x 64 cols, K=512 streamed in 32-chunks, 512 threads.
// fp32x2 packed FMA (FFMA2), A row-pairs packed as 64-bit operands.
#define BM 256
#define BK 32
#define AS_OFF 32768                 // after Bs (512*64 floats)
#define E2_OFF (AS_OFF + 2 * BK * BM)
#define P2_OFF (E2_OFF + BM)
#define RED_OFF (P2_OFF + GC)
#define SMEM_FLOATS (RED_OFF + 2)
#define SMEM_BYTES (SMEM_FLOATS * 4)
#define CPAD 65                      // cross-tile row stride (bank-conflict-free)

__global__ __launch_bounds__(512, 1) void k_main(
    const float* __restrict__ emb, const void* __restrict__ labels) {
    extern __shared__ float sm[];
    float* Bs = sm;                 // [512][64] prototypes, k-major (FULL K)
    float* As = sm + AS_OFF;        // [2][32][256] A tile, k-major, swizzled
    float* s_e2 = sm + E2_OFF;      // [256]
    float* s_p2 = sm + P2_OFF;      // [64]
    float* s_loss = sm + RED_OFF;
    int* s_corr = (int*)(sm + RED_OFF + 1);

    const int tid = threadIdx.x;
    const int row0 = blockIdx.x * BM;

    // Load full prototype matrix into SMEM (contiguous, coalesced)
    {
        const float4* src = (const float4*)g_protoT;
        float4* dst = (float4*)Bs;
#pragma unroll
        for (int i = tid; i < (GD * GC) / 4; i += 512) dst[i] = src[i];
    }
    if (tid < BM) s_e2[tid] = g_e2[row0 + tid];
    if (tid < GC) s_p2[tid] = g_p2[tid];
    if (tid == 0) { *s_loss = 0.0f; *s_corr = 0; }

    const int tx = tid & 15;   // col group: cols tx*4 .. tx*4+3
    const int ty = tid >> 4;   // row group: rows ty*8 .. ty*8+7
    const int ty8 = ty * 8;
    const int tx4 = tx * 4;

    unsigned long long acc[4][4];
#pragma unroll
    for (int p = 0; p < 4; p++)
#pragma unroll
        for (int n = 0; n < 4; n++) acc[p][n] = 0ULL;

    // Loader mapping: idx = tid + it*512; r = idx>>3 (row), k4 = idx&7
    int lr[4], lk4[4];
#pragma unroll
    for (int it = 0; it < 4; it++) {
        int idx = tid + it * 512;
        lr[it] = idx >> 3;
        lk4[it] = idx & 7;
    }
    float4 v[4];

#define LOAD_CHUNK(T)                                                        \
    {                                                                        \
        _Pragma("unroll") for (int it = 0; it < 4; it++) {                   \
            v[it] = *(const float4*)(emb + (size_t)(row0 + lr[it]) * GD +    \
                                     (T)*BK + lk4[it] * 4);                  \
        }                                                                    \
    }
#define STORE_CHUNK(BUF)                                                     \
    {                                                                        \
        float* A = As + (BUF) * (BK * BM);                                   \
        _Pragma("unroll") for (int it = 0; it < 4; it++) {                   \
            int rr = lr[it], k4 = lk4[it];                                   \
            int col = rr ^ (k4 << 2); /* XOR swizzle -> conflict-free */     \
            float* p = A + (k4 * 4) * BM + col;                              \
            p[0 * BM] = v[it].x;                                             \
            p[1 * BM] = v[it].y;                                             \
            p[2 * BM] = v[it].z;                                             \
            p[3 * BM] = v[it].w;                                             \
        }                                                                    \
    }

    LOAD_CHUNK(0);
    STORE_CHUNK(0);
    __syncthreads();

#pragma unroll 1
    for (int t = 0; t < GD / BK; t++) {
        const int buf = t & 1;
        if (t + 1 < GD / BK) LOAD_CHUNK(t + 1);  // overlap LDG with compute
        const float* A = As + buf * (BK * BM);
        const float* Brow = Bs + t * BK * GC;
#pragma unroll
        for (int k = 0; k < BK; k++) {
            const int sw = k & 28;  // (k>>2)<<2 : matches store swizzle
            const float* arow = A + k * BM;
            ulonglong2 a01 =
                *(const ulonglong2*)(arow + ((ty8 + 0) ^ sw));  // rows ty8+0..3
            ulonglong2 a23 =
                *(const ulonglong2*)(arow + ((ty8 + 4) ^ sw));  // rows ty8+4..7
            float4 bv = *(const float4*)(Brow + k * GC + tx4);
            unsigned long long b0 = dup2(bv.x);
            unsigned long long b1 = dup2(bv.y);
            unsigned long long b2 = dup2(bv.z);
            unsigned long long b3 = dup2(bv.w);
            ffma2(acc[0][0], a01.x, b0);
            ffma2(acc[0][1], a01.x, b1);
            ffma2(acc[0][2], a01.x, b2);
            ffma2(acc[0][3], a01.x, b3);
            ffma2(acc[1][0], a01.y, b0);
            ffma2(acc[1][1], a01.y, b1);
            ffma2(acc[1][2], a01.y, b2);
            ffma2(acc[1][3], a01.y, b3);
            ffma2(acc[2][0], a23.x, b0);
            ffma2(acc[2][1], a23.x, b1);
            ffma2(acc[2][2], a23.x, b2);
            ffma2(acc[2][3], a23.x, b3);
            ffma2(acc[3][0], a23.y, b0);
            ffma2(acc[3][1], a23.y, b1);
            ffma2(acc[3][2], a23.y, b2);
            ffma2(acc[3][3], a23.y, b3);
        }
        __syncthreads();
        if (t + 1 < GD / BK) {
            STORE_CHUNK((t + 1) & 1);
            __syncthreads();
        }
    }

    // Spill cross-products into (now dead) Bs region, padded stride 65
    float* s_cross = Bs;  // [256][CPAD] floats = 16640 <= 32768
#pragma unroll
    for (int p = 0; p < 4; p++) {
#pragma unroll
        for (int n = 0; n < 4; n++) {
            unsigned long long a = acc[p][n];
            float lo = __uint_as_float((unsigned)(a & 0xffffffffULL));
            float hi = __uint_as_float((unsigned)(a >> 32));
            s_cross[(ty8 + 2 * p + 0) * CPAD + tx4 + n] = lo;
            s_cross[(ty8 + 2 * p + 1) * CPAD + tx4 + n] = hi;
        }
    }
    __syncthreads();

    // Per-row epilogue: distances -> logits -> log-softmax -> nll / argmax
    if (tid < BM) {
        const int r = tid;
        const int lab = get_label(labels, row0 + r) & (GC - 1);
        const float e2 = s_e2[r];
        float* cr = s_cross + r * CPAD;
        float mx = -3.0e38f;
        int bi = 0;
#pragma unroll 8
        for (int c = 0; c < GC; c++) {
            float d2 = e2 + s_p2[c] - 2.0f * cr[c];
            d2 = fmaxf(d2, 1e-12f);
            float lg = -sqrtf(d2);
            cr[c] = lg;  // overwrite in place
            if (lg > mx) { mx = lg; bi = c; }
        }
        float se = 0.0f;
#pragma unroll 8
        for (int c = 0; c < GC; c++) se += __expf(cr[c] - mx);
        float nll = (mx + __logf(se)) - cr[lab];
        atomicAdd(s_loss, nll);
        if (bi == lab) atomicAdd(s_corr, 1);
    }
    __syncthreads();
    if (tid == 0) {
        atomicAdd(&g_loss, *s_loss);
        atomicAdd(&g_correct, *s_corr);
    }
#undef LOAD_CHUNK
#undef STORE_CHUNK
}

// ------------------------- K6: finalize outputs -----------------------------
__global__ void k_final(float* out, int out_size) {
    if (threadIdx.x == 0 && blockIdx.x == 0) {
        out[0] = g_loss / (float)GN;
        if (out_size > 1) out[1] = (float)g_correct / (float)GN;
    }
}

// ------------------------- launch -------------------------------------------
extern "C" void kernel_launch(void* const* d_in, const int* in_sizes, int n_in,
                              void* d_out, int out_size) {
    const float* emb = (const float*)d_in[0];
    const void* labels = d_in[1];
    float* out = (float*)d_out;

    cudaFuncSetAttribute(k_main, cudaFuncAttributeMaxDynamicSharedMemorySize,
                         SMEM_BYTES);

    k_zero<<<GN / 256, 256>>>((const int*)labels);
    k_hist<<<64, 256>>>(labels);
    k_scatter<<<GN / 256, 256>>>(labels);
    k_psum<<<GC * 2, 512>>>(emb);  // 128 blocks x 4 groups = 512 groups
    k_proto<<<GC, 512>>>();
    k_main<<<GN / BM, 512, SMEM_BYTES>>>(emb, labels);
    k_final<<<1, 32>>>(out, out_size);
}